// round 1
// baseline (speedup 1.0000x reference)
#include <cuda_runtime.h>
#include <cuda_bf16.h>
#include <math.h>

// Stickbreaking attention, B=1, H=16, S=2048, Dh=64, fp32.
//
// Key structural fact (fp32-faithful): the reference adds -1e9 to log_beta
// BEFORE the reverse cumsum over keys. Every query row i < S-1 therefore has
// re_cum <= -1e9 for all j, and expf underflows to exactly 0.0f, making
// weights and the output exactly (+/-)0 for those rows. Only the last query
// row (i = S-1) of each head is nonzero:
//   l_j   = (q_{S-1} . k_j) / sqrt(Dh)
//   S_j   = sum_{j'=j}^{S-1} log_sigmoid(-l_{j'})   (reverse inclusive scan)
//   w_j   = sigmoid(l_j) * exp(S_j)
//   out_d = sum_j w_j * v[j][d]

#define SB_H  16
#define SB_S  2048
#define SB_D  64
#define SB_SCALE 0.125f   // 1/sqrt(64)

// ---------------------------------------------------------------------------
// Kernel 1: zero the whole output (rows 0..S-2 are exactly zero; row S-1 is
// overwritten by kernel 2, which runs after on the same stream).
// ---------------------------------------------------------------------------
__global__ void sb_zero_kernel(float4* __restrict__ out, int n4) {
    int i = blockIdx.x * blockDim.x + threadIdx.x;
    if (i < n4) out[i] = make_float4(0.f, 0.f, 0.f, 0.f);
}

// ---------------------------------------------------------------------------
// Kernel 2: one block per head, 512 threads. Computes the last query row.
// ---------------------------------------------------------------------------
__global__ __launch_bounds__(512, 1)
void sb_lastrow_kernel(const float* __restrict__ q,
                       const float* __restrict__ k,
                       const float* __restrict__ v,
                       float* __restrict__ out) {
    const int h   = blockIdx.x;
    const int tid = threadIdx.x;
    const int lane = tid & 31;
    const int wid  = tid >> 5;          // 16 warps

    __shared__ float qs[SB_D];          // q_{S-1} for this head
    __shared__ float arr[SB_S];         // phase1: logits l_j ; phase2: weights w_j
    __shared__ float warpsum[16];
    __shared__ float warpoff[16];
    __shared__ float red[8 * SB_D];     // phase-3 partial sums

    // ---- load q row (last query of head h) ----
    const size_t head_base = (size_t)h * SB_S * SB_D;
    if (tid < SB_D) qs[tid] = q[head_base + (size_t)(SB_S - 1) * SB_D + tid];
    __syncthreads();

    // ---- phase 1: logits l_j = (q . k_j) * scale, all j ----
    const float4* qs4 = reinterpret_cast<const float4*>(qs);
    #pragma unroll
    for (int u = 0; u < 4; u++) {
        int j = tid + u * 512;
        const float4* krow = reinterpret_cast<const float4*>(k + head_base + (size_t)j * SB_D);
        float acc = 0.f;
        #pragma unroll
        for (int i = 0; i < 16; i++) {
            float4 kv = krow[i];
            float4 qv = qs4[i];
            acc += kv.x * qv.x + kv.y * qv.y + kv.z * qv.z + kv.w * qv.w;
        }
        arr[j] = acc * SB_SCALE;
    }
    __syncthreads();

    // ---- phase 2: reverse inclusive scan of p_j = log_sigmoid(-l_j),
    //      then w_j = sigmoid(l_j) * exp(S_j), written in place into arr.
    // t = S-1-j runs forward; thread owns t in [tid*4, tid*4+4).
    float loc[4];
    float lval[4];
    float run = 0.f;
    #pragma unroll
    for (int u = 0; u < 4; u++) {
        int t = tid * 4 + u;
        int j = SB_S - 1 - t;
        float l = arr[j];
        lval[u] = l;
        // log_sigmoid(-l) = -softplus(l) = -(max(l,0) + log1p(exp(-|l|)))
        float sp = fmaxf(l, 0.f) + log1pf(expf(-fabsf(l)));
        run += (-sp);
        loc[u] = run;                    // local inclusive prefix (in t order)
    }
    // warp inclusive scan of per-thread totals
    float tot = run;
    float sc  = tot;
    #pragma unroll
    for (int off = 1; off < 32; off <<= 1) {
        float n = __shfl_up_sync(0xFFFFFFFFu, sc, off);
        if (lane >= off) sc += n;
    }
    if (lane == 31) warpsum[wid] = sc;   // warp total (inclusive of all lanes)
    __syncthreads();
    if (wid == 0) {
        float wv = (lane < 16) ? warpsum[lane] : 0.f;
        float ws = wv;
        #pragma unroll
        for (int off = 1; off < 16; off <<= 1) {
            float n = __shfl_up_sync(0xFFFFFFFFu, ws, off);
            if (lane >= off) ws += n;
        }
        if (lane < 16) warpoff[lane] = ws - wv;   // exclusive warp offset
    }
    __syncthreads();
    const float thread_excl = (sc - tot) + warpoff[wid];
    #pragma unroll
    for (int u = 0; u < 4; u++) {
        int t = tid * 4 + u;
        int j = SB_S - 1 - t;
        float S_j = thread_excl + loc[u];
        float l   = lval[u];
        float z   = 1.f / (1.f + expf(-l));       // sigmoid(l)
        arr[j] = z * expf(S_j);                   // w_j (expf underflow -> 0)
    }
    __syncthreads();

    // ---- phase 3: out_d = sum_j w_j * v[j][d] ----
    // 512 threads = 8 j-groups x 64 dims; coalesced v reads across d.
    const int g = tid >> 6;       // 0..7
    const int d = tid & 63;
    float acc = 0.f;
    const float* vh = v + head_base;
    #pragma unroll 4
    for (int j = g * 256; j < g * 256 + 256; j++) {
        acc += arr[j] * vh[(size_t)j * SB_D + d];
    }
    red[tid] = acc;               // red[g*64+d] == red[tid]
    __syncthreads();
    if (tid < SB_D) {
        float s = 0.f;
        #pragma unroll
        for (int gg = 0; gg < 8; gg++) s += red[gg * SB_D + tid];
        out[head_base + (size_t)(SB_S - 1) * SB_D + tid] = s;
    }
}

// ---------------------------------------------------------------------------
extern "C" void kernel_launch(void* const* d_in, const int* in_sizes, int n_in,
                              void* d_out, int out_size) {
    const float* q = (const float*)d_in[0];
    const float* k = (const float*)d_in[1];
    const float* v = (const float*)d_in[2];
    float* out = (float*)d_out;

    int n4 = out_size / 4;   // 2,097,152 floats -> 524,288 float4
    sb_zero_kernel<<<(n4 + 255) / 256, 256>>>((float4*)out, n4);
    sb_lastrow_kernel<<<SB_H, 512>>>(q, k, v, out);
}

// round 2
// speedup vs baseline: 2.7800x; 2.7800x over previous
#include <cuda_runtime.h>
#include <cuda_bf16.h>
#include <math.h>

// Stickbreaking attention, B=1, H=16, S=2048, Dh=64, fp32.
//
// Structural facts (fp32-faithful):
//  (1) Mask-before-cumsum makes every query row except i=S-1 exactly zero
//      (exp underflow of -1e9 carry).
//  (2) For row S-1: S_j = sum_{j'>=j} log_sigmoid(-l_{j'}) is monotone
//      non-increasing as j decreases (terms <= 0). Once the running carry
//      drops below -120, expf(S_j)==0.0f exactly for all remaining j, so
//      those keys contribute bitwise zero and can be skipped exactly.
//
// One fused kernel: blocks 0..15 compute head h's last row (processing keys
// from the end in 512-wide chunks with early exit); blocks 16..NB-1 zero the
// rest of the output (skipping the last-row slots owned by compute blocks).

#define SB_H  16
#define SB_S  2048
#define SB_D  64
#define SB_SCALE 0.125f        // 1/sqrt(64)
#define SB_CHUNK 512
#define SB_NBLK  512           // total blocks (16 compute + 496 zero)
#define SB_CUTOFF -120.0f      // expf(x)==0.0f for x < ~-104; margin included

__global__ __launch_bounds__(512, 1)
void sb_fused_kernel(const float* __restrict__ q,
                     const float* __restrict__ k,
                     const float* __restrict__ v,
                     float* __restrict__ out) {
    const int bid = blockIdx.x;
    const int tid = threadIdx.x;

    if (bid >= SB_H) {
        // ---------------- zero path ----------------
        // out as float4: 524288 total; per head 32768; last 16 of each head's
        // 32768 are the last row -> owned by the compute block, skip them.
        float4* o4 = reinterpret_cast<float4*>(out);
        const int total4 = SB_H * SB_S * SB_D / 4;          // 524288
        const int per_head4 = SB_S * SB_D / 4;              // 32768
        const int stride = (SB_NBLK - SB_H) * 512;
        for (int i = (bid - SB_H) * 512 + tid; i < total4; i += stride) {
            if ((i & (per_head4 - 1)) < per_head4 - (SB_D / 4))
                o4[i] = make_float4(0.f, 0.f, 0.f, 0.f);
        }
        return;
    }

    // ---------------- compute path: head h = bid ----------------
    const int h    = bid;
    const int lane = tid & 31;
    const int wid  = tid >> 5;                // 16 warps

    __shared__ float qs[SB_D];
    __shared__ float wsm[SB_CHUNK];           // weights for current chunk (t-indexed)
    __shared__ float warpsum[16];
    __shared__ float warpscan[16];            // inclusive scan of warp totals
    __shared__ float red[8 * SB_D];

    const size_t head_base = (size_t)h * SB_S * SB_D;
    if (tid < SB_D) qs[tid] = q[head_base + (size_t)(SB_S - 1) * SB_D + tid];
    __syncthreads();

    const float4* qs4 = reinterpret_cast<const float4*>(qs);
    const float* vh = v + head_base;

    const int g = tid >> 6;                   // 0..7  (matvec group)
    const int d = tid & 63;                   // dim
    float acc = 0.f;                          // out_d partial over this group's keys
    float carry = 0.f;                        // scan carry from processed chunks

    for (int c = 0; c < SB_S / SB_CHUNK; c++) {
        const int t = c * SB_CHUNK + tid;     // reverse index: t=0 -> j=S-1
        const int j = SB_S - 1 - t;

        // --- logit l_j = (q . k_j) * scale (register resident) ---
        const float4* krow = reinterpret_cast<const float4*>(k + head_base + (size_t)j * SB_D);
        float dot = 0.f;
        #pragma unroll
        for (int i = 0; i < 16; i++) {
            float4 kv = krow[i];
            float4 qv = qs4[i];
            dot += kv.x * qv.x + kv.y * qv.y + kv.z * qv.z + kv.w * qv.w;
        }
        const float l = dot * SB_SCALE;

        // --- p = log_sigmoid(-l) = -softplus(l), inclusive scan in t-order ---
        const float p = -(fmaxf(l, 0.f) + log1pf(expf(-fabsf(l))));
        float ws = p;
        #pragma unroll
        for (int off = 1; off < 32; off <<= 1) {
            float n = __shfl_up_sync(0xFFFFFFFFu, ws, off);
            if (lane >= off) ws += n;
        }
        if (lane == 31) warpsum[wid] = ws;
        __syncthreads();
        if (wid == 0) {
            float wv = (lane < 16) ? warpsum[lane] : 0.f;
            float s = wv;
            #pragma unroll
            for (int off = 1; off < 16; off <<= 1) {
                float n = __shfl_up_sync(0xFFFFFFFFu, s, off);
                if (lane >= off) s += n;
            }
            if (lane < 16) warpscan[lane] = s;     // inclusive over warps
        }
        __syncthreads();
        const float warp_excl = (wid == 0) ? 0.f : warpscan[wid - 1];
        const float S_t = carry + warp_excl + ws;  // inclusive scan value at t
        const float z = 1.f / (1.f + expf(-l));    // sigmoid(l)
        wsm[tid] = z * expf(S_t);                  // w_j (underflow -> exact 0)
        const float block_total = warpscan[15];
        __syncthreads();

        // --- matvec: this group's 64 keys of the chunk ---
        #pragma unroll 4
        for (int tt = g * 64; tt < g * 64 + 64; tt++) {
            const int jj = SB_S - 1 - (c * SB_CHUNK + tt);
            acc += wsm[tt] * vh[(size_t)jj * SB_D + d];
        }

        carry += block_total;
        if (carry < SB_CUTOFF) break;   // all remaining weights are exactly 0.0f
        __syncthreads();                // protect wsm before next chunk overwrite
    }

    // --- final reduce over the 8 groups ---
    red[tid] = acc;
    __syncthreads();
    if (tid < SB_D) {
        float s = 0.f;
        #pragma unroll
        for (int gg = 0; gg < 8; gg++) s += red[gg * SB_D + tid];
        out[head_base + (size_t)(SB_S - 1) * SB_D + tid] = s;
    }
}

extern "C" void kernel_launch(void* const* d_in, const int* in_sizes, int n_in,
                              void* d_out, int out_size) {
    const float* q = (const float*)d_in[0];
    const float* k = (const float*)d_in[1];
    const float* v = (const float*)d_in[2];
    float* out = (float*)d_out;
    sb_fused_kernel<<<SB_NBLK, 512>>>(q, k, v, out);
}

// round 3
// speedup vs baseline: 3.3293x; 1.1976x over previous
#include <cuda_runtime.h>
#include <cuda_bf16.h>
#include <math.h>

// Stickbreaking attention, B=1, H=16, S=2048, Dh=64, fp32.
//
// fp32-faithful structure:
//  (1) Mask(-1e9)-before-cumsum => every query row except i=S-1 is exactly 0
//      (expf underflow).
//  (2) Row S-1: S_j = sum_{j'>=j} log_sigmoid(-l_{j'}) is monotone
//      non-increasing going backward; once carry < -120, expf==0.0f exactly
//      for all remaining keys -> exact early exit.
//
// Single-wave fused kernel, grid=148: blocks 0..15 compute heads, 16..147
// zero the output (skipping last-row slots owned by compute blocks).

#define SB_H  16
#define SB_S  2048
#define SB_D  64
#define SB_SCALE 0.125f
#define SB_CHUNK 512
#define SB_NBLK  148
#define SB_CUTOFF -120.0f

__global__ __launch_bounds__(512, 1)
void sb_fused_kernel(const float* __restrict__ q,
                     const float* __restrict__ k,
                     const float* __restrict__ v,
                     float* __restrict__ out) {
    const int bid = blockIdx.x;
    const int tid = threadIdx.x;

    if (bid >= SB_H) {
        // ---------------- zero path (132 blocks, one wave) ----------------
        float4* o4 = reinterpret_cast<float4*>(out);
        const int total4 = SB_H * SB_S * SB_D / 4;     // 524288
        const int per_head4 = SB_S * SB_D / 4;         // 32768
        const int stride = (SB_NBLK - SB_H) * 512;     // 67584
        const float4 z4 = make_float4(0.f, 0.f, 0.f, 0.f);
        for (int i = (bid - SB_H) * 512 + tid; i < total4; i += stride) {
            if ((i & (per_head4 - 1)) < per_head4 - (SB_D / 4))
                o4[i] = z4;
        }
        return;
    }

    // ---------------- compute path: head h = bid ----------------
    const int h    = bid;
    const int lane = tid & 31;
    const int wid  = tid >> 5;                 // 16 warps

    __shared__ float  qs[SB_D];
    __shared__ float  wsm[SB_CHUNK];           // weights for current chunk (t-indexed)
    __shared__ float  warpsum[16];
    __shared__ float  warpscan[16];
    __shared__ float4 red4[512];               // [kgroup(32)][d4(16)]

    const size_t head_base = (size_t)h * SB_S * SB_D;
    if (tid < SB_D) qs[tid] = q[head_base + (size_t)(SB_S - 1) * SB_D + tid];
    __syncthreads();

    const float4* qs4 = reinterpret_cast<const float4*>(qs);
    const float4* vh4 = reinterpret_cast<const float4*>(v + head_base);

    const int kg = tid >> 4;                   // 0..31 key-group (16 keys each)
    const int d4 = tid & 15;                   // 0..15 float4 dim slot
    float4 acc = make_float4(0.f, 0.f, 0.f, 0.f);
    float carry = 0.f;

    for (int c = 0; c < SB_S / SB_CHUNK; c++) {
        const int t = c * SB_CHUNK + tid;      // reverse index: t=0 -> j=S-1
        const int j = SB_S - 1 - t;

        // --- logit l_j = (q . k_j) * scale (16 independent LDG.128) ---
        const float4* krow = reinterpret_cast<const float4*>(k + head_base + (size_t)j * SB_D);
        float dot = 0.f;
        #pragma unroll
        for (int i = 0; i < 16; i++) {
            float4 kv = krow[i];
            float4 qv = qs4[i];
            dot += kv.x * qv.x + kv.y * qv.y + kv.z * qv.z + kv.w * qv.w;
        }
        const float l = dot * SB_SCALE;

        // --- inclusive scan of p = -softplus(l) in t-order ---
        const float p = -(fmaxf(l, 0.f) + log1pf(expf(-fabsf(l))));
        float ws = p;
        #pragma unroll
        for (int off = 1; off < 32; off <<= 1) {
            float n = __shfl_up_sync(0xFFFFFFFFu, ws, off);
            if (lane >= off) ws += n;
        }
        if (lane == 31) warpsum[wid] = ws;
        __syncthreads();
        if (wid == 0) {
            float wv = (lane < 16) ? warpsum[lane] : 0.f;
            float s = wv;
            #pragma unroll
            for (int off = 1; off < 16; off <<= 1) {
                float n = __shfl_up_sync(0xFFFFFFFFu, s, off);
                if (lane >= off) s += n;
            }
            if (lane < 16) warpscan[lane] = s;
        }
        __syncthreads();
        const float warp_excl = (wid == 0) ? 0.f : warpscan[wid - 1];
        const float S_t = carry + warp_excl + ws;
        const float z = 1.f / (1.f + expf(-l));
        wsm[tid] = z * expf(S_t);              // exact 0 on underflow
        const float block_total = warpscan[15];
        __syncthreads();

        // --- matvec: 16 independent float4 V loads per thread (MLP=16) ---
        {
            const int tbase = c * SB_CHUNK + kg * 16;
            #pragma unroll
            for (int u = 0; u < 16; u++) {
                const int tt = kg * 16 + u;
                const int jj = SB_S - 1 - (tbase + u);
                const float  w  = wsm[tt];
                const float4 vv = vh4[(size_t)jj * (SB_D / 4) + d4];
                acc.x += w * vv.x;
                acc.y += w * vv.y;
                acc.z += w * vv.z;
                acc.w += w * vv.w;
            }
        }

        carry += block_total;
        if (carry < SB_CUTOFF) break;          // remaining weights exactly 0.0f
        __syncthreads();
    }

    // --- tree reduction over 32 kgroups ---
    red4[tid] = acc;
    __syncthreads();
    #pragma unroll
    for (int s = 16; s >= 1; s >>= 1) {
        if (kg < s) {
            float4 a = red4[kg * 16 + d4];
            float4 b = red4[(kg + s) * 16 + d4];
            a.x += b.x; a.y += b.y; a.z += b.z; a.w += b.w;
            red4[kg * 16 + d4] = a;
        }
        __syncthreads();
    }
    if (tid < 16) {
        float4* out4 = reinterpret_cast<float4*>(out + head_base + (size_t)(SB_S - 1) * SB_D);
        out4[tid] = red4[tid];
    }
}

extern "C" void kernel_launch(void* const* d_in, const int* in_sizes, int n_in,
                              void* d_out, int out_size) {
    const float* q = (const float*)d_in[0];
    const float* k = (const float*)d_in[1];
    const float* v = (const float*)d_in[2];
    float* out = (float*)d_out;
    sb_fused_kernel<<<SB_NBLK, 512>>>(q, k, v, out);
}

// round 5
// speedup vs baseline: 4.0882x; 1.2279x over previous
#include <cuda_runtime.h>
#include <cuda_bf16.h>
#include <math.h>
#include <cstdint>

// Stickbreaking attention, B=1, H=16, S=2048, Dh=64, fp32.
//
// fp32-faithful structure:
//  (1) Mask(-1e9)-before-cumsum => every query row except i=S-1 is exactly 0.
//  (2) Row S-1: suffix sums of log_sigmoid(-l) are monotone non-increasing;
//      once carry < -120, expf == 0.0f exactly for all remaining keys.
//
// Grid = 148 (one wave): blocks 0..15 compute heads (warp-specialized:
// warps 0-7 logits+scan, warps 8-15 cp.async V->SMEM), 16..147 zero output.

#define SB_H  16
#define SB_S  2048
#define SB_D  64
#define SB_SCALE 0.125f
#define SB_CHUNK 256
#define SB_NBLK  148
#define SB_CUTOFF -120.0f

// dynamic smem layout (bytes)
#define OFF_QS    0          // float[64]
#define OFF_WSM   256        // float[256]
#define OFF_WS8   1280       // float[8] warp totals
#define OFF_SC8   1312       // float[8] warp scan
#define OFF_V     2048       // float4[256*16] = 64 KB  (red4 aliases this)
#define SB_SMEM   (2048 + 65536)

__global__ __launch_bounds__(512, 1)
void sb_fused_kernel(const float* __restrict__ q,
                     const float* __restrict__ k,
                     const float* __restrict__ v,
                     float* __restrict__ out) {
    const int bid = blockIdx.x;
    const int tid = threadIdx.x;

    if (bid >= SB_H) {
        // ---------------- zero path ----------------
        float4* o4 = reinterpret_cast<float4*>(out);
        const int total4 = SB_H * SB_S * SB_D / 4;     // 524288
        const int per_head4 = SB_S * SB_D / 4;         // 32768
        const int stride = (SB_NBLK - SB_H) * 512;
        const float4 z4 = make_float4(0.f, 0.f, 0.f, 0.f);
        for (int i = (bid - SB_H) * 512 + tid; i < total4; i += stride) {
            if ((i & (per_head4 - 1)) < per_head4 - (SB_D / 4))
                o4[i] = z4;
        }
        return;
    }

    // ---------------- compute path: head h = bid ----------------
    extern __shared__ char smem[];
    float*  qs   = reinterpret_cast<float*>(smem + OFF_QS);
    float*  wsm  = reinterpret_cast<float*>(smem + OFF_WSM);
    float*  ws8  = reinterpret_cast<float*>(smem + OFF_WS8);
    float*  sc8  = reinterpret_cast<float*>(smem + OFF_SC8);
    float4* v_sm = reinterpret_cast<float4*>(smem + OFF_V);
    float4* red4 = reinterpret_cast<float4*>(smem + OFF_V);   // alias (post-matvec)
    const unsigned int v_sm_u32 =
        (unsigned int)__cvta_generic_to_shared(v_sm);

    const int h    = bid;
    const int lane = tid & 31;
    const int wid  = tid >> 5;

    const size_t head_base = (size_t)h * SB_S * SB_D;
    if (tid < SB_D) qs[tid] = q[head_base + (size_t)(SB_S - 1) * SB_D + tid];
    __syncthreads();

    const float4* qs4 = reinterpret_cast<const float4*>(qs);
    const float4* vh4 = reinterpret_cast<const float4*>(v + head_base);

    const int kg = tid >> 4;      // 0..31 (8 keys each)
    const int d4 = tid & 15;      // 0..15
    float4 acc = make_float4(0.f, 0.f, 0.f, 0.f);
    float carry = 0.f;

    for (int c = 0; c < SB_S / SB_CHUNK; c++) {
        float l = 0.f, ws = 0.f;

        if (tid < SB_CHUNK) {
            // --- logits: one key per thread, 16 independent LDG.128 ---
            const int t = c * SB_CHUNK + tid;
            const int j = SB_S - 1 - t;
            const float4* krow = reinterpret_cast<const float4*>(k + head_base + (size_t)j * SB_D);
            float dot = 0.f;
            #pragma unroll
            for (int i = 0; i < 16; i++) {
                float4 kv = krow[i];
                float4 qv = qs4[i];
                dot += kv.x * qv.x + kv.y * qv.y + kv.z * qv.z + kv.w * qv.w;
            }
            l = dot * SB_SCALE;
            // inclusive warp scan of p = -softplus(l)
            const float p = -(fmaxf(l, 0.f) + log1pf(expf(-fabsf(l))));
            ws = p;
            #pragma unroll
            for (int off = 1; off < 32; off <<= 1) {
                float n = __shfl_up_sync(0xFFFFFFFFu, ws, off);
                if (lane >= off) ws += n;
            }
            if (lane == 31) ws8[wid] = ws;
        } else {
            // --- concurrent cp.async of V chunk (64 KB) into SMEM ---
            const int qv = tid - SB_CHUNK;     // 0..255
            #pragma unroll
            for (int u = 0; u < 16; u++) {
                const int g = u * SB_CHUNK + qv;        // float4 index 0..4095
                const int tl = g >> 4;                  // key (t-local)
                const int dd = g & 15;
                const int jj = SB_S - 1 - (c * SB_CHUNK + tl);
                const float4* src = vh4 + (size_t)jj * 16 + dd;
                const unsigned int dst = v_sm_u32 + (unsigned int)g * 16u;
                asm volatile("cp.async.cg.shared.global [%0], [%1], 16;\n"
                             :: "r"(dst), "l"(src));
            }
            asm volatile("cp.async.commit_group;\n" ::: "memory");
        }
        __syncthreads();

        // --- scan across the 8 logit warps ---
        if (wid == 0) {
            float wv = (lane < 8) ? ws8[lane] : 0.f;
            float s = wv;
            #pragma unroll
            for (int off = 1; off < 8; off <<= 1) {
                float n = __shfl_up_sync(0xFFFFFFFFu, s, off);
                if (lane >= off) s += n;
            }
            if (lane < 8) sc8[lane] = s;
        }
        __syncthreads();

        if (tid < SB_CHUNK) {
            const float warp_excl = (wid == 0) ? 0.f : sc8[wid - 1];
            const float S_t = carry + warp_excl + ws;
            const float z = 1.f / (1.f + expf(-l));
            wsm[tid] = z * expf(S_t);            // exact 0 on underflow
        } else {
            asm volatile("cp.async.wait_group 0;\n" ::: "memory");
        }
        const float block_total = sc8[7];
        __syncthreads();

        // --- matvec from SMEM: 8 keys x 1 float4 per thread ---
        #pragma unroll
        for (int u = 0; u < 8; u++) {
            const int tt = kg * 8 + u;
            const float  w  = wsm[tt];
            const float4 vv = v_sm[tt * 16 + d4];
            acc.x += w * vv.x;
            acc.y += w * vv.y;
            acc.z += w * vv.z;
            acc.w += w * vv.w;
        }

        carry += block_total;
        if (carry < SB_CUTOFF) break;            // remaining weights exactly 0.0f
        __syncthreads();                          // protect smem before next chunk
    }

    // --- tree reduce over 32 kgroups (red4 aliases v_sm; sync first) ---
    __syncthreads();
    red4[tid] = acc;
    __syncthreads();
    #pragma unroll
    for (int s = 16; s >= 1; s >>= 1) {
        if (kg < s) {
            float4 a = red4[kg * 16 + d4];
            float4 b = red4[(kg + s) * 16 + d4];
            a.x += b.x; a.y += b.y; a.z += b.z; a.w += b.w;
            red4[kg * 16 + d4] = a;
        }
        __syncthreads();
    }
    if (tid < 16) {
        float4* out4 = reinterpret_cast<float4*>(out + head_base + (size_t)(SB_S - 1) * SB_D);
        out4[tid] = red4[tid];
    }
}

extern "C" void kernel_launch(void* const* d_in, const int* in_sizes, int n_in,
                              void* d_out, int out_size) {
    const float* q = (const float*)d_in[0];
    const float* k = (const float*)d_in[1];
    const float* v = (const float*)d_in[2];
    float* out = (float*)d_out;

    static bool attr_set = false;
    if (!attr_set) {
        cudaFuncSetAttribute(sb_fused_kernel,
                             cudaFuncAttributeMaxDynamicSharedMemorySize, SB_SMEM);
        attr_set = true;
    }
    sb_fused_kernel<<<SB_NBLK, 512, SB_SMEM>>>(q, k, v, out);
}